// round 15
// baseline (speedup 1.0000x reference)
#include <cuda_runtime.h>
#include <cuda_fp16.h>
#include <math.h>
#include <stdint.h>

#define Bz     4
#define Tt     2048
#define Dm     1024
#define Hh     16
#define Dh     64
#define Mrows  (Bz * Tt)     // 8192
#define QSCALE (0.125f * 1.44269504088896f)

// ---- scratch (fp16 data plane) ----
__device__ __half g_Xh[Mrows * Dm];
__device__ __half g_Wh[4][Dm * Dm];
__device__ __half g_Qh[Mrows * Dm];   // pre-scaled by QSCALE
__device__ __half g_Kh[Mrows * Dm];
__device__ __half g_Vh[Mrows * Dm];
__device__ __half g_ctxh[Mrows * Dm];

__device__ __forceinline__ uint32_t pack_h2(float a, float b) {
    __half2 h = __floats2half2_rn(a, b);
    return *(uint32_t*)&h;
}
__device__ __forceinline__ float ex2f(float x) {
    float r;
    asm("ex2.approx.ftz.f32 %0, %1;" : "=f"(r) : "f"(x));
    return r;
}
__device__ __forceinline__ uint32_t ex2_h2(uint32_t dh) {
    uint32_t r;
    asm("ex2.approx.f16x2 %0, %1;" : "=r"(r) : "r"(dh));
    return r;
}
__device__ __forceinline__ uint32_t smem_u32(const void* p) {
    return (uint32_t)__cvta_generic_to_shared(p);
}
__device__ __forceinline__ void cp16(uint32_t dst_smem, const void* src) {
    asm volatile("cp.async.cg.shared.global [%0], [%1], 16;\n" :: "r"(dst_smem), "l"(src));
}
#define CP_COMMIT() asm volatile("cp.async.commit_group;\n" ::: "memory")
#define CP_WAIT1()  asm volatile("cp.async.wait_group 1;\n" ::: "memory")
#define CP_WAIT0()  asm volatile("cp.async.wait_group 0;\n" ::: "memory")

#define LDMX4(r0,r1,r2,r3,addr) \
    asm volatile("ldmatrix.sync.aligned.m8n8.x4.shared.b16 {%0,%1,%2,%3}, [%4];" \
        : "=r"(r0),"=r"(r1),"=r"(r2),"=r"(r3) : "r"(addr))
#define LDMX4T(r0,r1,r2,r3,addr) \
    asm volatile("ldmatrix.sync.aligned.m8n8.x4.trans.shared.b16 {%0,%1,%2,%3}, [%4];" \
        : "=r"(r0),"=r"(r1),"=r"(r2),"=r"(r3) : "r"(addr))
#define LDMX2T(r0,r1,addr) \
    asm volatile("ldmatrix.sync.aligned.m8n8.x2.trans.shared.b16 {%0,%1}, [%2];" \
        : "=r"(r0),"=r"(r1) : "r"(addr))
#define MMA16816(acc,a,b0,b1) \
    asm volatile("mma.sync.aligned.m16n8k16.row.col.f32.f16.f16.f32 " \
        "{%0,%1,%2,%3}, {%4,%5,%6,%7}, {%8,%9}, {%0,%1,%2,%3};\n" \
        : "+f"((acc)[0]), "+f"((acc)[1]), "+f"((acc)[2]), "+f"((acc)[3]) \
        : "r"((a)[0]), "r"((a)[1]), "r"((a)[2]), "r"((a)[3]), "r"(b0), "r"(b1))

// ======================= prep: fp32 -> fp16 =======================
__global__ __launch_bounds__(256) void prep_w(const float* __restrict__ Wq,
                                              const float* __restrict__ Wk,
                                              const float* __restrict__ Wv,
                                              const float* __restrict__ Wo)
{
    const float* W = (blockIdx.z == 0) ? Wq : (blockIdx.z == 1) ? Wk :
                     (blockIdx.z == 2) ? Wv : Wo;
    __half* D = g_Wh[blockIdx.z];
    size_t i = ((size_t)blockIdx.x * 256 + threadIdx.x) * 4;
    float4 v = *(const float4*)(W + i);
    uint2 o = make_uint2(pack_h2(v.x, v.y), pack_h2(v.z, v.w));
    *(uint2*)&D[i] = o;
}
__global__ __launch_bounds__(256) void prep_x(const float* __restrict__ x)
{
    size_t i = ((size_t)blockIdx.x * 256 + threadIdx.x) * 4;
    float4 v = *(const float4*)(x + i);
    *(uint2*)&g_Xh[i] = make_uint2(pack_h2(v.x, v.y), pack_h2(v.z, v.w));
}

// ========== fp16 GEMM: 128x128x32 CTA tile, 4 warps @ 64x64, cp.async 2-stage ==========
#define GA_STRIDE_B 80
#define GB_STRIDE_B 304
#define GA_BYTES (128 * GA_STRIDE_B)   // 10240
#define GB_BYTES (32 * GB_STRIDE_B)    // 9728
#define GSTG (GA_BYTES + GB_BYTES)
#define GEMM_SMEM_BYTES (2 * GSTG)     // 39936
#define KITERS (Dm / 32)

__device__ __forceinline__ void gemm_f16_body(const __half* __restrict__ Ah,
                                              const __half* __restrict__ Bh,
                                              int mode, float* __restrict__ Cf)
{
    extern __shared__ __align__(16) char smem[];
    const uint32_t smb = smem_u32(smem);

    const int tid  = threadIdx.x;   // 0..127
    const int lane = tid & 31;
    const int warp = tid >> 5;
    const int wm   = warp >> 1;
    const int wn   = warp & 1;
    const int bM = blockIdx.y * 128;
    const int bN = blockIdx.x * 128;
    const int j  = lane >> 3;
    const int l7 = lane & 7;

    const __half* Ab = Ah + (size_t)bM * Dm;
    const __half* Bb = Bh + bN;

    float acc[4][8][4];
    #pragma unroll
    for (int mt = 0; mt < 4; mt++)
        #pragma unroll
        for (int nt = 0; nt < 8; nt++)
            #pragma unroll
            for (int i = 0; i < 4; i++) acc[mt][nt][i] = 0.f;

    auto stage = [&](int k0, int buf) {
        const uint32_t Ad = smb + buf * GSTG;
        const uint32_t Bd = Ad + GA_BYTES;
        #pragma unroll
        for (int i = 0; i < 4; i++) {
            int f = tid + i * 128;
            cp16(Ad + (f >> 2) * GA_STRIDE_B + (f & 3) * 16,
                 Ab + (size_t)(f >> 2) * Dm + k0 + (f & 3) * 8);
            cp16(Bd + (f >> 4) * GB_STRIDE_B + (f & 15) * 16,
                 Bb + (size_t)(k0 + (f >> 4)) * Dm + (f & 15) * 8);
        }
    };

    stage(0, 0);
    CP_COMMIT();

    for (int it = 0; it < KITERS; it++) {
        const int buf = it & 1;
        if (it + 1 < KITERS) stage((it + 1) * 32, buf ^ 1);
        CP_COMMIT();
        CP_WAIT1();
        __syncthreads();

        const uint32_t Ad = smb + buf * GSTG;
        const uint32_t Bd = Ad + GA_BYTES;
        #pragma unroll
        for (int ks = 0; ks < 2; ks++) {
            uint32_t af[4][4];
            #pragma unroll
            for (int mt = 0; mt < 4; mt++) {
                uint32_t a = Ad + (uint32_t)(wm * 64 + mt * 16 + (j & 1) * 8 + l7) * GA_STRIDE_B
                           + (ks * 16 + (j >> 1) * 8) * 2;
                LDMX4(af[mt][0], af[mt][1], af[mt][2], af[mt][3], a);
            }
            #pragma unroll
            for (int pr = 0; pr < 4; pr++) {
                uint32_t b0, b1, b2, b3;
                uint32_t a = Bd + (uint32_t)(ks * 16 + (j & 1) * 8 + l7) * GB_STRIDE_B
                           + (wn * 64 + pr * 16 + (j >> 1) * 8) * 2;
                LDMX4T(b0, b1, b2, b3, a);
                #pragma unroll
                for (int mt = 0; mt < 4; mt++) {
                    MMA16816(acc[mt][2 * pr],     af[mt], b0, b1);
                    MMA16816(acc[mt][2 * pr + 1], af[mt], b2, b3);
                }
            }
        }
        __syncthreads();
    }

    const int ar = lane >> 2;
    const int ac = lane & 3;
    const float sc = (mode == 0) ? QSCALE : 1.f;
    #pragma unroll
    for (int mt = 0; mt < 4; mt++) {
        const int row0 = bM + wm * 64 + mt * 16 + ar;
        #pragma unroll
        for (int nt = 0; nt < 8; nt++) {
            const int col = bN + wn * 64 + nt * 8 + ac * 2;
            if (mode == 3) {
                *(float2*)(Cf + (size_t)row0 * Dm + col)       = make_float2(acc[mt][nt][0], acc[mt][nt][1]);
                *(float2*)(Cf + (size_t)(row0 + 8) * Dm + col) = make_float2(acc[mt][nt][2], acc[mt][nt][3]);
            } else {
                __half* Ch = (mode == 0) ? g_Qh : (mode == 1) ? g_Kh : g_Vh;
                *(uint32_t*)&Ch[(size_t)row0 * Dm + col] =
                    pack_h2(acc[mt][nt][0] * sc, acc[mt][nt][1] * sc);
                *(uint32_t*)&Ch[(size_t)(row0 + 8) * Dm + col] =
                    pack_h2(acc[mt][nt][2] * sc, acc[mt][nt][3] * sc);
            }
        }
    }
}

__global__ __launch_bounds__(128, 2) void gemm_qkv()
{
    gemm_f16_body(g_Xh, g_Wh[blockIdx.z], (int)blockIdx.z, nullptr);
}
__global__ __launch_bounds__(128, 2) void gemm_out(float* __restrict__ out)
{
    gemm_f16_body(g_ctxh, g_Wh[3], 3, out);
}

// ======================= fp16 causal flash attention =======================
// 256 threads (8 warps); warp w owns 16 query rows; 128 q rows/CTA; key tiles of 64.
// Double-buffered K/V; l computed via ones-column MMA; P via ex2.approx.f16x2.
#define AT_STRIDE_B 144
#define AQ_BYTES (128 * AT_STRIDE_B)   // 18432
#define AK_BYTES (64 * AT_STRIDE_B)    // 9216
#define ATTN_SMEM_BYTES (AQ_BYTES + 4 * AK_BYTES)   // 55296 (Q + 2x (K+V))

__global__ __launch_bounds__(256, 2) void attn_mma()
{
    extern __shared__ __align__(16) char smem[];
    const uint32_t smQ = smem_u32(smem);

    const int tid  = threadIdx.x;
    const int lane = tid & 31;
    const int warp = tid >> 5;
    const int ar   = lane >> 2;
    const int ac   = lane & 3;
    const int j    = lane >> 3;
    const int l7   = lane & 7;

    // big-qt blocks first (wave load balance)
    const int qt = (gridDim.x - 1) - blockIdx.x;
    const int h = blockIdx.y, b = blockIdx.z;
    const int q0 = qt * 128;

    // ---- stage Q (fp16, pre-scaled) : group 1 ----
    const __half* Qg = g_Qh + ((size_t)(b * Tt + q0)) * Dm + h * Dh;
    #pragma unroll
    for (int i = 0; i < 4; i++) {
        int f = tid + i * 256;
        cp16(smQ + (f >> 3) * AT_STRIDE_B + (f & 7) * 16,
             Qg + (size_t)(f >> 3) * Dm + (f & 7) * 8);
    }
    CP_COMMIT();

    auto stage_kv = [&](int kt, int buf) {
        const uint32_t smK = smQ + AQ_BYTES + buf * 2 * AK_BYTES;
        const uint32_t smV = smK + AK_BYTES;
        const __half* Kg = g_Kh + ((size_t)(b * Tt + kt * 64)) * Dm + h * Dh;
        const __half* Vg = g_Vh + ((size_t)(b * Tt + kt * 64)) * Dm + h * Dh;
        #pragma unroll
        for (int i = 0; i < 2; i++) {
            int f = tid + i * 256;
            cp16(smK + (f >> 3) * AT_STRIDE_B + (f & 7) * 16,
                 Kg + (size_t)(f >> 3) * Dm + (f & 7) * 8);
            cp16(smV + (f >> 3) * AT_STRIDE_B + (f & 7) * 16,
                 Vg + (size_t)(f >> 3) * Dm + (f & 7) * 8);
        }
    };

    stage_kv(0, 0);        // group 2
    CP_COMMIT();

    // ---- init ones column (col 64) of BOTH V buffers (cols 64-71 never touched by cp.async) ----
    {
        const int row = tid >> 2, q = tid & 3;
        const uint32_t val = (q == 0) ? 0x00003C00u : 0u;   // halves (1.0, 0.0)
        #pragma unroll
        for (int bufi = 0; bufi < 2; bufi++) {
            char* vrow = smem + AQ_BYTES + bufi * 2 * AK_BYTES + AK_BYTES
                       + row * AT_STRIDE_B + 128;
            *(uint32_t*)(vrow + q * 4) = val;
        }
    }

    float accO[8][4];
    #pragma unroll
    for (int nt = 0; nt < 8; nt++)
        #pragma unroll
        for (int i = 0; i < 4; i++) accO[nt][i] = 0.f;
    float accL[4] = {0.f, 0.f, 0.f, 0.f};

    float mrow0 = -1e30f, mrow1 = -1e30f;
    const int ntiles = 2 * qt + 2;

    for (int kt = 0; kt < ntiles; kt++) {
        const int buf = kt & 1;
        const uint32_t smK = smQ + AQ_BYTES + buf * 2 * AK_BYTES;
        const uint32_t smV = smK + AK_BYTES;

        __syncthreads();               // all warps done with buf^1 (tile kt-1)
        if (kt + 1 < ntiles) {
            stage_kv(kt + 1, buf ^ 1); // prefetch next tile
            CP_COMMIT();
            CP_WAIT1();                // tile kt (and Q) arrived
        } else {
            CP_WAIT0();
        }
        __syncthreads();

        // ---- S = Q K^T (warp: 16 x 64), 4 ksteps of k16 ----
        float s[8][4];
        #pragma unroll
        for (int nt = 0; nt < 8; nt++)
            #pragma unroll
            for (int i = 0; i < 4; i++) s[nt][i] = 0.f;

        #pragma unroll
        for (int ks = 0; ks < 4; ks++) {
            uint32_t qa[4];
            uint32_t aq = smQ + (uint32_t)(warp * 16 + (j & 1) * 8 + l7) * AT_STRIDE_B
                        + (ks * 16 + (j >> 1) * 8) * 2;
            LDMX4(qa[0], qa[1], qa[2], qa[3], aq);
            #pragma unroll
            for (int pr = 0; pr < 4; pr++) {
                uint32_t b0, b1, b2, b3;
                uint32_t akd = smK + (uint32_t)(pr * 16 + (j >> 1) * 8 + l7) * AT_STRIDE_B
                             + (ks * 16 + (j & 1) * 8) * 2;
                LDMX4(b0, b1, b2, b3, akd);
                MMA16816(s[2 * pr],     qa, b0, b1);
                MMA16816(s[2 * pr + 1], qa, b2, b3);
            }
        }

        // ---- mask + online softmax (log2 domain) ----
        const int r0 = q0 + warp * 16 + ar;
        if (kt >= 2 * qt) {
            #pragma unroll
            for (int nt = 0; nt < 8; nt++) {
                const int c0 = kt * 64 + nt * 8 + 2 * ac;
                if (c0     > r0    ) s[nt][0] = -1e30f;
                if (c0 + 1 > r0    ) s[nt][1] = -1e30f;
                if (c0     > r0 + 8) s[nt][2] = -1e30f;
                if (c0 + 1 > r0 + 8) s[nt][3] = -1e30f;
            }
        }
        float mx0 = -1e30f, mx1 = -1e30f;
        #pragma unroll
        for (int nt = 0; nt < 8; nt++) {
            mx0 = fmaxf(mx0, fmaxf(s[nt][0], s[nt][1]));
            mx1 = fmaxf(mx1, fmaxf(s[nt][2], s[nt][3]));
        }
        mx0 = fmaxf(mx0, __shfl_xor_sync(0xffffffff, mx0, 1));
        mx0 = fmaxf(mx0, __shfl_xor_sync(0xffffffff, mx0, 2));
        mx1 = fmaxf(mx1, __shfl_xor_sync(0xffffffff, mx1, 1));
        mx1 = fmaxf(mx1, __shfl_xor_sync(0xffffffff, mx1, 2));

        const float mn0 = fmaxf(mrow0, mx0);
        const float mn1 = fmaxf(mrow1, mx1);
        const float corr0 = ex2f(mrow0 - mn0);
        const float corr1 = ex2f(mrow1 - mn1);
        mrow0 = mn0; mrow1 = mn1;

        // P = 2^(s-mn) straight to packed fp16 via ex2.approx.f16x2
        uint32_t ph[8][2];
        #pragma unroll
        for (int nt = 0; nt < 8; nt++) {
            ph[nt][0] = ex2_h2(pack_h2(s[nt][0] - mn0, s[nt][1] - mn0));
            ph[nt][1] = ex2_h2(pack_h2(s[nt][2] - mn1, s[nt][3] - mn1));
        }

        #pragma unroll
        for (int nt = 0; nt < 8; nt++) {
            accO[nt][0] *= corr0; accO[nt][1] *= corr0;
            accO[nt][2] *= corr1; accO[nt][3] *= corr1;
        }
        accL[0] *= corr0; accL[1] *= corr0;
        accL[2] *= corr1; accL[3] *= corr1;

        // ---- O += P V ; l += P * ones  (ones-column MMA) ----
        #pragma unroll
        for (int jk = 0; jk < 4; jk++) {
            uint32_t pa[4] = { ph[2 * jk][0], ph[2 * jk][1], ph[2 * jk + 1][0], ph[2 * jk + 1][1] };
            #pragma unroll
            for (int pr = 0; pr < 4; pr++) {
                uint32_t v0, v1, v2, v3;
                uint32_t av = smV + (uint32_t)(jk * 16 + (j & 1) * 8 + l7) * AT_STRIDE_B
                            + (pr * 16 + (j >> 1) * 8) * 2;
                LDMX4T(v0, v1, v2, v3, av);
                MMA16816(accO[2 * pr],     pa, v0, v1);
                MMA16816(accO[2 * pr + 1], pa, v2, v3);
            }
            uint32_t o0, o1;
            uint32_t av1 = smV + (uint32_t)(jk * 16 + ((lane >> 3) & 1) * 8 + l7) * AT_STRIDE_B + 128;
            LDMX2T(o0, o1, av1);
            MMA16816(accL, pa, o0, o1);
        }
    }

    // ---- normalize + store ctx as fp16 ----
    const float l0 = __shfl_sync(0xffffffff, accL[0], lane & ~3);
    const float l1 = __shfl_sync(0xffffffff, accL[2], lane & ~3);
    const float inv0 = 1.f / l0;
    const float inv1 = 1.f / l1;
    const int r0 = q0 + warp * 16 + ar;
    __half* og = g_ctxh + ((size_t)(b * Tt)) * Dm + h * Dh;
    #pragma unroll
    for (int nt = 0; nt < 8; nt++) {
        const int col = nt * 8 + 2 * ac;
        *(uint32_t*)&og[(size_t)r0 * Dm + col] =
            pack_h2(accO[nt][0] * inv0, accO[nt][1] * inv0);
        *(uint32_t*)&og[(size_t)(r0 + 8) * Dm + col] =
            pack_h2(accO[nt][2] * inv1, accO[nt][3] * inv1);
    }
}

// ======================= launch =======================
extern "C" void kernel_launch(void* const* d_in, const int* in_sizes, int n_in,
                              void* d_out, int out_size)
{
    const float* x  = (const float*)d_in[0];
    const float* Wq = (const float*)d_in[1];
    const float* Wk = (const float*)d_in[2];
    const float* Wv = (const float*)d_in[3];
    const float* Wo = (const float*)d_in[4];
    float* out = (float*)d_out;

    cudaFuncSetAttribute(gemm_qkv, cudaFuncAttributeMaxDynamicSharedMemorySize, GEMM_SMEM_BYTES);
    cudaFuncSetAttribute(gemm_out, cudaFuncAttributeMaxDynamicSharedMemorySize, GEMM_SMEM_BYTES);
    cudaFuncSetAttribute(attn_mma, cudaFuncAttributeMaxDynamicSharedMemorySize, ATTN_SMEM_BYTES);

    prep_w<<<dim3((Dm * Dm / 4) / 256, 1, 4), 256>>>(Wq, Wk, Wv, Wo);
    prep_x<<<(Mrows * Dm / 4) / 256, 256>>>(x);

    gemm_qkv<<<dim3(Dm / 128, Mrows / 128, 3), 128, GEMM_SMEM_BYTES>>>();

    attn_mma<<<dim3(Tt / 128, Hh, Bz), 256, ATTN_SMEM_BYTES>>>();

    gemm_out<<<dim3(Dm / 128, Mrows / 128, 1), 128, GEMM_SMEM_BYTES>>>(out);
}